// round 13
// baseline (speedup 1.0000x reference)
#include <cuda_runtime.h>
#include <cuda_bf16.h>
#include <math.h>
#include <stdint.h>

#define BATCH      4096
#define DIM        128
#define NFORM      256
#define NLIT       10752
#define NTILES     112

// ---------------------------------------------------------------------------
// Helpers
// ---------------------------------------------------------------------------
__device__ __forceinline__ float ftanh(float v) {
    float r; asm("tanh.approx.f32 %0, %1;" : "=f"(r) : "f"(v)); return r;
}
__device__ __forceinline__ uint32_t smem_u32(const void* p) {
    uint32_t a;
    asm("{ .reg .u64 t; cvta.to.shared.u64 t, %1; cvt.u32.u64 %0, t; }" : "=r"(a) : "l"(p));
    return a;
}
__device__ __forceinline__ uint32_t rna_tf32(float v) {
    uint32_t r; asm("cvt.rna.tf32.f32 %0, %1;" : "=r"(r) : "f"(v)); return r;
}
__device__ __forceinline__ void mma_tf32(float* c, uint4 a, uint32_t b0, uint32_t b1) {
    asm volatile("mma.sync.aligned.m16n8k8.row.col.f32.tf32.tf32.f32 "
                 "{%0,%1,%2,%3}, {%4,%5,%6,%7}, {%8,%9}, {%0,%1,%2,%3};"
                 : "+f"(c[0]), "+f"(c[1]), "+f"(c[2]), "+f"(c[3])
                 : "r"(a.x), "r"(a.y), "r"(a.z), "r"(a.w), "r"(b0), "r"(b1));
}
__device__ __forceinline__ void cpa16(uint32_t dst, const void* src) {
    asm volatile("cp.async.ca.shared.global [%0], [%1], 16;" :: "r"(dst), "l"(src));
}
__device__ __forceinline__ void cpa_commit() { asm volatile("cp.async.commit_group;"); }
__device__ __forceinline__ void cpa_wait1()  { asm volatile("cp.async.wait_group 1;"); }
__device__ __forceinline__ void cpa_wait0()  { asm volatile("cp.async.wait_group 0;"); }

// ---------------------------------------------------------------------------
// Conj-aligned slot tables.  S2P[g][tig][s] = pair index within 64-block
// literal span (-1 = pad).  BMASK[g][tig] bit s = conj ends at slot s.
// ---------------------------------------------------------------------------
__constant__ int8_t S2P[4][4][8] = {
  { { 0, 2, 3, 6, 7, 8,-1,-1}, { 1, 4, 5, 9,10,11,-1,-1},
    {12,14,15,18,19,20,-1,-1}, {13,16,17,21,22,23,-1,-1} },
  { { 0, 3, 4, 9,10,11,-1,-1}, { 1, 5, 6,12,13,14,-1,-1},
    { 2, 7, 8,-1,-1,-1,-1,-1}, {15,16,17,-1,-1,-1,-1,-1} },
  { { 0, 4, 5,12,13,14,-1,-1}, { 1, 6, 7,15,16,17,-1,-1},
    { 2, 8, 9,18,19,20,-1,-1}, { 3,10,11,21,22,23,-1,-1} },
  { {15,16,17,18,19,20, 5, 6}, {21,22,23,24,25,26, 0, 1},
    {27,28,29, 7, 8, 9,10, 2}, {11,12,13,14, 3, 4,-1,-1} }
};
__constant__ uint8_t BMASK[4][4] = {
  {0x25, 0x25, 0x25, 0x25},
  {0x25, 0x25, 0x05, 0x04},
  {0x25, 0x25, 0x25, 0x25},
  {0xA4, 0xE4, 0xD4, 0x3A}
};

// 112-tile decode: yy -> group, first formula, literal base, lits per 64-block
__device__ __forceinline__ void decode_tile(int yy, int& g, int& f0g, int& lb0,
                                            int& blkLit) {
    if (yy < 16)      { g = 0; f0g = 4 * yy;              lb0 = 96 * yy;          blkLit = 48; }
    else if (yy < 48) { int t = yy - 16; g = 1; f0g = 64  + 2 * t; lb0 = 1536 + 72 * t;  blkLit = 36; }
    else if (yy < 80) { int t = yy - 48; g = 2; f0g = 128 + 2 * t; lb0 = 3840 + 96 * t;  blkLit = 48; }
    else              { int t = yy - 80; g = 3; f0g = 192 + 2 * t; lb0 = 6912 + 120 * t; blkLit = 60; }
}

// ---------------------------------------------------------------------------
// Scratch (device globals)
// ---------------------------------------------------------------------------
__device__ float g_dnnf[BATCH * NFORM];
__device__ float g_loc [BATCH * NFORM];
__device__ float g_c   [NFORM];
__device__ float g_bp  [NTILES * 128];          // permuted bias per tile
__device__ uint4 g_xa [32 * 4096];
__device__ uint4 g_wb [NTILES * 4096];
__device__ uint4 g_xa2[128 * 2048];
__device__ uint4 g_b2 [8 * 2048];

// ---------------------------------------------------------------------------
// K0a: x -> k1 A blob + k2 A blob (grid=128, 32 rows each)
// ---------------------------------------------------------------------------
#define PREP2_SMEM (32 * 132 * 4)
__global__ __launch_bounds__(256) void k0_prep_xa(const float* __restrict__ x) {
    extern __shared__ __align__(16) float xs[];
    const int xb = blockIdx.x, tid = threadIdx.x;
    const int rb = xb >> 2, sub = xb & 3;
    for (int e = tid; e < 32 * 32; e += 256) {
        int r = e >> 5, c4 = e & 31;
        float4 v = reinterpret_cast<const float4*>(x + (size_t)(xb * 32 + r) * DIM)[c4];
        xs[r * 132 + c4 * 4 + 0] = v.x;
        xs[r * 132 + c4 * 4 + 1] = v.y;
        xs[r * 132 + c4 * 4 + 2] = v.z;
        xs[r * 132 + c4 * 4 + 3] = v.w;
    }
    __syncthreads();
    #pragma unroll
    for (int i = 0; i < 4; ++i) {
        int o = i * 256 + tid;
        int lane = o & 31, ks = (o >> 5) & 3, mt = (o >> 7) & 1, kc = (o >> 8) & 3;
        int r = mt * 16 + (lane >> 2);
        int c = kc * 32 + ks * 8 + (lane & 3);
        int go = kc * 1024 + sub * 256 + mt * 128 + ks * 32 + lane;
        g_xa[(size_t)rb * 4096 + go] =
            make_uint4(rna_tf32(xs[r * 132 + c]),     rna_tf32(xs[(r + 8) * 132 + c]),
                       rna_tf32(xs[r * 132 + c + 4]), rna_tf32(xs[(r + 8) * 132 + c + 4]));
    }
    #pragma unroll
    for (int i = 0; i < 8; ++i) {
        int o = i * 256 + tid;
        int lane = o & 31, ks = (o >> 5) & 3, wm = (o >> 7) & 1, kc = (o >> 8) & 7;
        int r = wm * 16 + (lane >> 2);
        int c = kc * 32 + ks * 8 + (lane & 3);
        float v0, v1, v2, v3;
        if (c < 128) {
            float a = xs[r * 132 + c],      b = xs[(r + 8) * 132 + c];
            float d = xs[r * 132 + c + 4],  e = xs[(r + 8) * 132 + c + 4];
            v0 = a * a; v1 = b * b; v2 = d * d; v3 = e * e;
        } else {
            int cc = c - 128;
            v0 = xs[r * 132 + cc];     v1 = xs[(r + 8) * 132 + cc];
            v2 = xs[r * 132 + cc + 4]; v3 = xs[(r + 8) * 132 + cc + 4];
        }
        g_xa2[(size_t)xb * 2048 + o] =
            make_uint4(rna_tf32(v0), rna_tf32(v1), rna_tf32(v2), rna_tf32(v3));
    }
}

// ---------------------------------------------------------------------------
// K0b: masked W -> conj-permuted k1 B blob + permuted bias blob
// ---------------------------------------------------------------------------
#define PREP_SMEM (128 * 132 * 4)
__global__ __launch_bounds__(256) void k0_prep_wb(const float* __restrict__ w,
                                                  const float* __restrict__ lm,
                                                  const float* __restrict__ bias) {
    extern __shared__ __align__(16) float ws[];          // [128 k][132 cols]
    const int yy = blockIdx.x, tid = threadIdx.x;
    int g, f0g, lb0, blkLit;
    decode_tile(yy, g, f0g, lb0, blkLit);

    for (int e = tid; e < 128 * 128; e += 256) {
        int k = e >> 7, j = e & 127;
        int blk = j >> 6, jj = j & 63;
        int nt = jj >> 3, tig = (jj >> 1) & 3, b = jj & 1;
        int p = S2P[g][tig][nt];
        float val = 0.f;
        if (p >= 0) {
            int lit = lb0 + blk * blkLit + 2 * p + b;
            int f = f0g + ((g == 0) ? (blk * 2 + (p >= 12)) : blk);
            float mk = (fabsf(lm[k * NFORM + f]) > 1.0f) ? 1.0f : 0.0f;
            val = w[(size_t)k * NLIT + lit] * mk;
        }
        ws[k * 132 + j] = val;
    }
    __syncthreads();
    #pragma unroll
    for (int i = 0; i < 16; ++i) {
        int o = i * 256 + tid;
        int lane = o & 31, p = (o >> 5) & 3, ks = (o >> 7) & 3;
        int wn = (o >> 9) & 1, kc = (o >> 10) & 3;
        int n = wn * 64 + p * 16 + (lane >> 2);
        int k = kc * 32 + ks * 8 + (lane & 3);
        g_wb[(size_t)yy * 4096 + o] =
            make_uint4(rna_tf32(ws[k * 132 + n]),     rna_tf32(ws[(k + 4) * 132 + n]),
                       rna_tf32(ws[k * 132 + n + 8]), rna_tf32(ws[(k + 4) * 132 + n + 8]));
    }
    // permuted bias
    if (tid < 128) {
        int j = tid;
        int blk = j >> 6, jj = j & 63;
        int nt = jj >> 3, tig = (jj >> 1) & 3, b = jj & 1;
        int p = S2P[g][tig][nt];
        g_bp[yy * 128 + j] = (p >= 0) ? bias[lb0 + blk * blkLit + 2 * p + b] : 0.f;
    }
}

// ---------------------------------------------------------------------------
// K0c: k2 B blob + c[f]
// ---------------------------------------------------------------------------
__device__ __forceinline__ float b2val(const float* mu, const float* sg, int k, int n) {
    if (k < 128) { float s = sg[n * DIM + k]; return s * s; }
    int kk = k - 128;
    float s = sg[n * DIM + kk];
    return -2.f * mu[n * DIM + kk] * s * s;
}
__global__ __launch_bounds__(256) void k0_prep_b2c(const float* __restrict__ mu,
                                                   const float* __restrict__ sigma) {
    const int b = blockIdx.x, tid = threadIdx.x;
    if (b < 8) {
        #pragma unroll
        for (int i = 0; i < 8; ++i) {
            int o = i * 256 + tid;
            int lane = o & 31, p = (o >> 5) & 3, ks = (o >> 7) & 3, wn = (o >> 9) & 3;
            int n = wn * 64 + p * 16 + (lane >> 2);
            int k = b * 32 + ks * 8 + (lane & 3);
            g_b2[(size_t)b * 2048 + o] =
                make_uint4(rna_tf32(b2val(mu, sigma, k,     n)),
                           rna_tf32(b2val(mu, sigma, k + 4, n)),
                           rna_tf32(b2val(mu, sigma, k,     n + 8)),
                           rna_tf32(b2val(mu, sigma, k + 4, n + 8)));
        }
    } else {
        int f = tid;
        const float4* m4 = reinterpret_cast<const float4*>(mu + f * DIM);
        const float4* s4 = reinterpret_cast<const float4*>(sigma + f * DIM);
        float c = 0.f;
        #pragma unroll 8
        for (int i = 0; i < 32; ++i) {
            float4 m = m4[i], s = s4[i];
            c += m.x * m.x * s.x * s.x + m.y * m.y * s.y * s.y
               + m.z * m.z * s.z * s.z + m.w * m.w * s.w * s.w;
        }
        g_c[f] = c;
    }
}

// ---------------------------------------------------------------------------
// K1: single-pass TF32 GEMM + fully register-resident segmented reduce
// ---------------------------------------------------------------------------
#define K1_ST(s) ((s) * 32768)
#define K1_SMEM  (3 * 32768)

__device__ __forceinline__ void k1_prefetch(int kc, uint32_t st, int tid, int rb, int yy) {
    const uint4* asrc = g_xa + (size_t)rb * 4096 + kc * 1024;
    const uint4* bsrc = g_wb + (size_t)yy * 4096 + kc * 1024;
    #pragma unroll
    for (int i = 0; i < 4; ++i) {
        int e = tid + i * 256;
        cpa16(st + e * 16,         asrc + e);
        cpa16(st + 16384 + e * 16, bsrc + e);
    }
}

__global__ __launch_bounds__(256, 2) void k1_tensor() {
    extern __shared__ __align__(1024) char smem[];
    const uint32_t sb = smem_u32(smem);

    const int tid  = threadIdx.x;
    const int wid  = tid >> 5;
    const int lane = tid & 31;
    const int rb   = blockIdx.x;
    const int yy   = blockIdx.y;
    const int rowBase = rb * 128;

    int g, f0g, lb0, blkLit;
    decode_tile(yy, g, f0g, lb0, blkLit);

    k1_prefetch(0, sb + K1_ST(0), tid, rb, yy);
    cpa_commit();
    k1_prefetch(1, sb + K1_ST(1), tid, rb, yy);
    cpa_commit();

    const int wm = wid & 3, wn = wid >> 2;
    const int mrow = wm * 32, ncol = wn * 64;
    const uint32_t aoff = (uint32_t)(wm * 4096 + lane * 16);
    const uint32_t boff = (uint32_t)(16384 + wn * 8192 + lane * 16);

    float acc[8][2][4];
    #pragma unroll
    for (int nt = 0; nt < 8; ++nt)
        #pragma unroll
        for (int mt = 0; mt < 2; ++mt)
            #pragma unroll
            for (int j = 0; j < 4; ++j) acc[nt][mt][j] = 0.f;

    #pragma unroll
    for (int kc = 0; kc < 4; ++kc) {
        if (kc < 3) cpa_wait1(); else cpa_wait0();
        __syncthreads();
        if (kc < 2) {
            k1_prefetch(kc + 2, sb + K1_ST((kc + 2) % 3), tid, rb, yy);
            cpa_commit();
        }
        const char* st = smem + K1_ST(kc % 3);
        #pragma unroll
        for (int ks = 0; ks < 4; ++ks) {
            uint4 av[2];
            av[0] = *reinterpret_cast<const uint4*>(st + aoff + ks * 512);
            av[1] = *reinterpret_cast<const uint4*>(st + aoff + 2048 + ks * 512);
            #pragma unroll
            for (int p = 0; p < 4; ++p) {
                uint4 bv = *reinterpret_cast<const uint4*>(st + boff + ks * 2048 + p * 512);
                #pragma unroll
                for (int mt = 0; mt < 2; ++mt) {
                    mma_tf32(acc[2*p    ][mt], av[mt], bv.x, bv.y);
                    mma_tf32(acc[2*p + 1][mt], av[mt], bv.z, bv.w);
                }
            }
        }
    }

    // ---- register-resident epilogue: conjs are thread-local pairs ----
    const int tig = lane & 3, gidr = lane >> 2;
    const uint32_t bm = BMASK[g][tig];
    const float ndv = (float)(2 + g);

    float bv0[8], bv1[8];
    #pragma unroll
    for (int s = 0; s < 8; ++s) {
        bv0[s] = __ldg(&g_bp[yy * 128 + ncol + s * 8 + 2 * tig]);
        bv1[s] = __ldg(&g_bp[yy * 128 + ncol + s * 8 + 2 * tig + 1]);
    }

    #pragma unroll
    for (int q = 0; q < 4; ++q) {
        const int mt = q >> 1, h = q & 1;
        float fs = 0.f, cs = 0.f;
        float cnt = 0.f;
        #pragma unroll
        for (int s = 0; s < 8; ++s) {
            float pv = ftanh(acc[s][mt][h * 2] + bv0[s]) +
                       ftanh(acc[s][mt][h * 2 + 1] + bv1[s]);
            cs += pv;
            cnt += 1.f;
            if ((bm >> s) & 1) {
                fs += ftanh(cs - 2.f * cnt + 1.5f);
                cs = 0.f; cnt = 0.f;
            }
        }
        fs += __shfl_xor_sync(0xFFFFFFFFu, fs, 1);
        if (g != 0) fs += __shfl_xor_sync(0xFFFFFFFFu, fs, 2);
        const float outv = ftanh(fs + 3.f * ndv - 1.5f);
        const int row = rowBase + mrow + mt * 16 + h * 8 + gidr;
        if (g == 0) {
            if (tig == 0) g_dnnf[(size_t)row * NFORM + f0g + wn * 2]     = outv;
            if (tig == 2) g_dnnf[(size_t)row * NFORM + f0g + wn * 2 + 1] = outv;
        } else {
            if (tig == 0) g_dnnf[(size_t)row * NFORM + f0g + wn] = outv;
        }
    }
}

// ---------------------------------------------------------------------------
// K2 (TF32, K=256): v -> loc -> row softmax -> g_loc
// ---------------------------------------------------------------------------
#define K2_ST(s) (1024 + (s) * 36864)
#define K2_SMEM  (1024 + 3 * 36864)

__device__ __forceinline__ void k2_prefetch(int kc, uint32_t st, int tid, int xb) {
    const uint4* asrc = g_xa2 + (size_t)xb * 2048 + kc * 256;
    const uint4* bsrc = g_b2 + (size_t)kc * 2048;
    cpa16(st + tid * 16, asrc + tid);
    #pragma unroll
    for (int i = 0; i < 8; ++i) {
        int e = tid + i * 256;
        cpa16(st + 4096 + e * 16, bsrc + e);
    }
}

__global__ __launch_bounds__(256) void k2_loc(const float* __restrict__ temp) {
    extern __shared__ __align__(1024) char smem[];
    const uint32_t sb = smem_u32(smem);
    float* scr = reinterpret_cast<float*>(smem);

    const int tid  = threadIdx.x;
    const int wid  = tid >> 5;
    const int lane = tid & 31;
    const int xb   = blockIdx.x;
    const int rowBase = xb * 32;

    k2_prefetch(0, sb + K2_ST(0), tid, xb);
    cpa_commit();
    k2_prefetch(1, sb + K2_ST(1), tid, xb);
    cpa_commit();

    const int wm = wid & 1, wn = wid >> 1;
    const int mrow = wm * 16, ncol = wn * 64;
    const uint32_t aoff = (uint32_t)(wm * 2048 + lane * 16);
    const uint32_t boff = (uint32_t)(4096 + wn * 8192 + lane * 16);

    float acc[8][4];
    #pragma unroll
    for (int nt = 0; nt < 8; ++nt)
        #pragma unroll
        for (int j = 0; j < 4; ++j) acc[nt][j] = 0.f;

    #pragma unroll
    for (int kc = 0; kc < 8; ++kc) {
        if (kc < 7) cpa_wait1(); else cpa_wait0();
        __syncthreads();
        if (kc < 6) {
            k2_prefetch(kc + 2, sb + K2_ST((kc + 2) % 3), tid, xb);
            cpa_commit();
        }
        const char* st = smem + K2_ST(kc % 3);
        #pragma unroll
        for (int ks = 0; ks < 4; ++ks) {
            uint4 av = *reinterpret_cast<const uint4*>(st + aoff + ks * 512);
            #pragma unroll
            for (int p = 0; p < 4; ++p) {
                uint4 bv = *reinterpret_cast<const uint4*>(st + boff + ks * 2048 + p * 512);
                mma_tf32(acc[2*p    ], av, bv.x, bv.y);
                mma_tf32(acc[2*p + 1], av, bv.z, bv.w);
            }
        }
    }

    const float s = 1.f / (1.f + __expf(-temp[0]));
    const int gidr = lane >> 2, tig = lane & 3;

    #pragma unroll
    for (int nt = 0; nt < 8; ++nt)
        #pragma unroll
        for (int j = 0; j < 4; ++j) {
            const int col = ncol + nt * 8 + 2 * tig + (j & 1);
            float v = acc[nt][j] + __ldg(&g_c[col]);
            acc[nt][j] = s * __expf(-__fsqrt_rn(fmaxf(v, 0.f)));
        }

    float rmax[2], rsum[2];
    #pragma unroll
    for (int hf = 0; hf < 2; ++hf) {
        float m = -1e30f;
        #pragma unroll
        for (int nt = 0; nt < 8; ++nt) {
            m = fmaxf(m, acc[nt][2*hf]);
            m = fmaxf(m, acc[nt][2*hf + 1]);
        }
        m = fmaxf(m, __shfl_xor_sync(0xFFFFFFFFu, m, 1));
        m = fmaxf(m, __shfl_xor_sync(0xFFFFFFFFu, m, 2));
        if (tig == 0) scr[(mrow + gidr + hf * 8) * 4 + wn] = m;
    }
    __syncthreads();
    #pragma unroll
    for (int hf = 0; hf < 2; ++hf) {
        const float* p = &scr[(mrow + gidr + hf * 8) * 4];
        rmax[hf] = fmaxf(fmaxf(p[0], p[1]), fmaxf(p[2], p[3]));
    }
    __syncthreads();

    #pragma unroll
    for (int hf = 0; hf < 2; ++hf) {
        float sm = 0.f;
        #pragma unroll
        for (int nt = 0; nt < 8; ++nt) {
            acc[nt][2*hf]     = __expf(acc[nt][2*hf]     - rmax[hf]);
            acc[nt][2*hf + 1] = __expf(acc[nt][2*hf + 1] - rmax[hf]);
            sm += acc[nt][2*hf] + acc[nt][2*hf + 1];
        }
        sm += __shfl_xor_sync(0xFFFFFFFFu, sm, 1);
        sm += __shfl_xor_sync(0xFFFFFFFFu, sm, 2);
        if (tig == 0) scr[(mrow + gidr + hf * 8) * 4 + wn] = sm;
    }
    __syncthreads();
    #pragma unroll
    for (int hf = 0; hf < 2; ++hf) {
        const float* p = &scr[(mrow + gidr + hf * 8) * 4];
        rsum[hf] = 1.f / (p[0] + p[1] + p[2] + p[3]);
    }

    #pragma unroll
    for (int hf = 0; hf < 2; ++hf) {
        const size_t grow = (size_t)(rowBase + mrow + gidr + hf * 8);
        const float inv = rsum[hf];
        #pragma unroll
        for (int nt = 0; nt < 8; ++nt) {
            const int col = ncol + nt * 8 + 2 * tig;
            const size_t idx = grow * NFORM + col;
            g_loc[idx]     = acc[nt][2*hf]     * inv;
            g_loc[idx + 1] = acc[nt][2*hf + 1] * inv;
        }
    }
}

// ---------------------------------------------------------------------------
// K3: out = dnnf * loc
// ---------------------------------------------------------------------------
__global__ __launch_bounds__(256) void k3_mul(float* __restrict__ out) {
    const size_t i = (size_t)blockIdx.x * 256 + threadIdx.x;
    float4 a = reinterpret_cast<const float4*>(g_dnnf)[i];
    float4 b = reinterpret_cast<const float4*>(g_loc)[i];
    reinterpret_cast<float4*>(out)[i] =
        make_float4(a.x * b.x, a.y * b.y, a.z * b.z, a.w * b.w);
}

// ---------------------------------------------------------------------------
extern "C" void kernel_launch(void* const* d_in, const int* in_sizes, int n_in,
                              void* d_out, int out_size) {
    const float* x     = (const float*)d_in[0];
    const float* w     = (const float*)d_in[1];
    const float* bias  = (const float*)d_in[2];
    const float* lm    = (const float*)d_in[3];
    const float* mu    = (const float*)d_in[4];
    const float* sigma = (const float*)d_in[5];
    const float* temp  = (const float*)d_in[6];
    float* out = (float*)d_out;

    cudaFuncSetAttribute(k0_prep_xa, cudaFuncAttributeMaxDynamicSharedMemorySize, PREP2_SMEM);
    cudaFuncSetAttribute(k0_prep_wb, cudaFuncAttributeMaxDynamicSharedMemorySize, PREP_SMEM);
    cudaFuncSetAttribute(k1_tensor,  cudaFuncAttributeMaxDynamicSharedMemorySize, K1_SMEM);
    cudaFuncSetAttribute(k2_loc,     cudaFuncAttributeMaxDynamicSharedMemorySize, K2_SMEM);

    cudaStream_t s2;
    cudaStreamCreateWithFlags(&s2, cudaStreamNonBlocking);
    cudaEvent_t evXA, evK2;
    cudaEventCreateWithFlags(&evXA, cudaEventDisableTiming);
    cudaEventCreateWithFlags(&evK2, cudaEventDisableTiming);

    k0_prep_xa<<<128, 256, PREP2_SMEM>>>(x);
    cudaEventRecord(evXA, 0);
    cudaStreamWaitEvent(s2, evXA, 0);
    k0_prep_wb<<<NTILES, 256, PREP_SMEM>>>(w, lm, bias);
    k0_prep_b2c<<<9, 256, 0, s2>>>(mu, sigma);
    k2_loc<<<BATCH / 32, 256, K2_SMEM, s2>>>(temp);
    cudaEventRecord(evK2, s2);
    k1_tensor<<<dim3(32, NTILES), 256, K1_SMEM>>>();
    cudaStreamWaitEvent(0, evK2, 0);
    k3_mul<<<BATCH * NFORM / 1024, 256>>>(out);
}

// round 14
// speedup vs baseline: 1.3665x; 1.3665x over previous
#include <cuda_runtime.h>
#include <cuda_bf16.h>
#include <math.h>
#include <stdint.h>

#define BATCH      4096
#define DIM        128
#define NFORM      256
#define NLIT       10752

// ---------------------------------------------------------------------------
// Helpers (portable PTX only: mma.sync / cp.async / cvt.rna.tf32)
// ---------------------------------------------------------------------------
__device__ __forceinline__ float ftanh(float v) {
    float r; asm("tanh.approx.f32 %0, %1;" : "=f"(r) : "f"(v)); return r;
}
__device__ __forceinline__ uint32_t smem_u32(const void* p) {
    uint32_t a;
    asm("{ .reg .u64 t; cvta.to.shared.u64 t, %1; cvt.u32.u64 %0, t; }" : "=r"(a) : "l"(p));
    return a;
}
__device__ __forceinline__ uint32_t rna_tf32(float v) {
    uint32_t r; asm("cvt.rna.tf32.f32 %0, %1;" : "=r"(r) : "f"(v)); return r;
}
__device__ __forceinline__ void mma_tf32(float* c, uint4 a, uint32_t b0, uint32_t b1) {
    asm volatile("mma.sync.aligned.m16n8k8.row.col.f32.tf32.tf32.f32 "
                 "{%0,%1,%2,%3}, {%4,%5,%6,%7}, {%8,%9}, {%0,%1,%2,%3};"
                 : "+f"(c[0]), "+f"(c[1]), "+f"(c[2]), "+f"(c[3])
                 : "r"(a.x), "r"(a.y), "r"(a.z), "r"(a.w), "r"(b0), "r"(b1));
}
__device__ __forceinline__ void cpa16(uint32_t dst, const void* src) {
    asm volatile("cp.async.ca.shared.global [%0], [%1], 16;" :: "r"(dst), "l"(src));
}
__device__ __forceinline__ void cpa_commit() { asm volatile("cp.async.commit_group;"); }
__device__ __forceinline__ void cpa_wait1()  { asm volatile("cp.async.wait_group 1;"); }
__device__ __forceinline__ void cpa_wait0()  { asm volatile("cp.async.wait_group 0;"); }

// ---------------------------------------------------------------------------
// Scratch (device globals)
// ---------------------------------------------------------------------------
__device__ float g_dnnf[BATCH * NFORM];
__device__ float g_loc [BATCH * NFORM];
__device__ float g_c   [NFORM];
__device__ uint4 g_xa [32 * 4096];      // k1 A: tf32 fragments, per 128-row block
__device__ uint4 g_wb [99 * 4096];      // k1 B: tf32 fragments, per yy-tile
__device__ uint4 g_xa2[128 * 2048];     // k2 A: [x^2 || x], per 32-row block
__device__ uint4 g_b2 [8 * 2048];       // k2 B: [sigma^2 ; -2 mu sigma^2]

// ---------------------------------------------------------------------------
// yy-tile decode (k1) — dense packed, 99 tiles
// ---------------------------------------------------------------------------
__device__ __forceinline__ void decode_tile(int yy, int& LF, int& nd, int& nf,
                                            int& f0g, int& lb0) {
    if (yy < 13)      { LF = 24; nd = 2; nf = (yy == 12) ? 4 : 5; f0g = 5 * yy;          lb0 = 120 * yy; }
    else if (yy < 35) { int t = yy - 13; LF = 36; nd = 3; nf = (t == 21) ? 1 : 3; f0g = 64  + 3 * t; lb0 = 1536 + 108 * t; }
    else if (yy < 67) { int t = yy - 35; LF = 48; nd = 4; nf = 2; f0g = 128 + 2 * t; lb0 = 3840 + 96 * t; }
    else              { int t = yy - 67; LF = 60; nd = 5; nf = 2; f0g = 192 + 2 * t; lb0 = 6912 + 120 * t; }
}

// ---------------------------------------------------------------------------
// K0a: x -> k1 A blob (g_xa) + k2 A blob (g_xa2).  grid=128, 32 rows per CTA.
// ---------------------------------------------------------------------------
#define PREP2_SMEM (32 * 132 * 4)
__global__ __launch_bounds__(256) void k0_prep_xa(const float* __restrict__ x) {
    extern __shared__ __align__(16) float xs[];          // [32][132]
    const int xb = blockIdx.x, tid = threadIdx.x;
    const int rb = xb >> 2, sub = xb & 3;
    for (int e = tid; e < 32 * 32; e += 256) {
        int r = e >> 5, c4 = e & 31;
        float4 v = reinterpret_cast<const float4*>(x + (size_t)(xb * 32 + r) * DIM)[c4];
        xs[r * 132 + c4 * 4 + 0] = v.x;
        xs[r * 132 + c4 * 4 + 1] = v.y;
        xs[r * 132 + c4 * 4 + 2] = v.z;
        xs[r * 132 + c4 * 4 + 3] = v.w;
    }
    __syncthreads();
    // k1 blob: 1024 entries (wm == sub)
    #pragma unroll
    for (int i = 0; i < 4; ++i) {
        int o = i * 256 + tid;
        int lane = o & 31, ks = (o >> 5) & 3, mt = (o >> 7) & 1, kc = (o >> 8) & 3;
        int r = mt * 16 + (lane >> 2);
        int c = kc * 32 + ks * 8 + (lane & 3);
        int go = kc * 1024 + sub * 256 + mt * 128 + ks * 32 + lane;
        g_xa[(size_t)rb * 4096 + go] =
            make_uint4(rna_tf32(xs[r * 132 + c]),     rna_tf32(xs[(r + 8) * 132 + c]),
                       rna_tf32(xs[r * 132 + c + 4]), rna_tf32(xs[(r + 8) * 132 + c + 4]));
    }
    // k2 blob: 2048 entries for this 32-row block
    #pragma unroll
    for (int i = 0; i < 8; ++i) {
        int o = i * 256 + tid;
        int lane = o & 31, ks = (o >> 5) & 3, wm = (o >> 7) & 1, kc = (o >> 8) & 7;
        int r = wm * 16 + (lane >> 2);
        int c = kc * 32 + ks * 8 + (lane & 3);
        float v0, v1, v2, v3;
        if (c < 128) {
            float a = xs[r * 132 + c],      b = xs[(r + 8) * 132 + c];
            float d = xs[r * 132 + c + 4],  e = xs[(r + 8) * 132 + c + 4];
            v0 = a * a; v1 = b * b; v2 = d * d; v3 = e * e;
        } else {
            int cc = c - 128;
            v0 = xs[r * 132 + cc];     v1 = xs[(r + 8) * 132 + cc];
            v2 = xs[r * 132 + cc + 4]; v3 = xs[(r + 8) * 132 + cc + 4];
        }
        g_xa2[(size_t)xb * 2048 + o] =
            make_uint4(rna_tf32(v0), rna_tf32(v1), rna_tf32(v2), rna_tf32(v3));
    }
}

// ---------------------------------------------------------------------------
// K0b: masked W -> k1 B blob (g_wb), per yy-tile, zero-padded
// ---------------------------------------------------------------------------
#define PREP_SMEM (128 * 132 * 4)
__global__ __launch_bounds__(256) void k0_prep_wb(const float* __restrict__ w,
                                                  const float* __restrict__ lm) {
    extern __shared__ __align__(16) float ws[];          // [128 k][132 n]
    const int yy = blockIdx.x, tid = threadIdx.x;
    int LF, nd, nf, f0g, lb0;
    decode_tile(yy, LF, nd, nf, f0g, lb0);
    const int LIVE = nf * LF;
    for (int e = tid; e < 128 * 128; e += 256) {
        int k = e >> 7, j = e & 127;
        float val = 0.f;
        if (j < LIVE) {
            int f = f0g + j / LF;
            float mk = (fabsf(lm[k * NFORM + f]) > 1.0f) ? 1.0f : 0.0f;
            val = w[(size_t)k * NLIT + lb0 + j] * mk;
        }
        ws[k * 132 + j] = val;
    }
    __syncthreads();
    #pragma unroll
    for (int i = 0; i < 16; ++i) {
        int o = i * 256 + tid;
        int lane = o & 31, p = (o >> 5) & 3, ks = (o >> 7) & 3;
        int wn = (o >> 9) & 1, kc = (o >> 10) & 3;
        int n = wn * 64 + p * 16 + (lane >> 2);
        int k = kc * 32 + ks * 8 + (lane & 3);
        g_wb[(size_t)yy * 4096 + o] =
            make_uint4(rna_tf32(ws[k * 132 + n]),     rna_tf32(ws[(k + 4) * 132 + n]),
                       rna_tf32(ws[k * 132 + n + 8]), rna_tf32(ws[(k + 4) * 132 + n + 8]));
    }
}

// ---------------------------------------------------------------------------
// K0c: k2 B blob (g_b2) + c[f].  grid = 9
// ---------------------------------------------------------------------------
__device__ __forceinline__ float b2val(const float* mu, const float* sg, int k, int n) {
    if (k < 128) { float s = sg[n * DIM + k]; return s * s; }
    int kk = k - 128;
    float s = sg[n * DIM + kk];
    return -2.f * mu[n * DIM + kk] * s * s;
}
__global__ __launch_bounds__(256) void k0_prep_b2c(const float* __restrict__ mu,
                                                   const float* __restrict__ sigma) {
    const int b = blockIdx.x, tid = threadIdx.x;
    if (b < 8) {
        #pragma unroll
        for (int i = 0; i < 8; ++i) {
            int o = i * 256 + tid;
            int lane = o & 31, p = (o >> 5) & 3, ks = (o >> 7) & 3, wn = (o >> 9) & 3;
            int n = wn * 64 + p * 16 + (lane >> 2);
            int k = b * 32 + ks * 8 + (lane & 3);
            g_b2[(size_t)b * 2048 + o] =
                make_uint4(rna_tf32(b2val(mu, sigma, k,     n)),
                           rna_tf32(b2val(mu, sigma, k + 4, n)),
                           rna_tf32(b2val(mu, sigma, k,     n + 8)),
                           rna_tf32(b2val(mu, sigma, k + 4, n + 8)));
        }
    } else {
        int f = tid;
        const float4* m4 = reinterpret_cast<const float4*>(mu + f * DIM);
        const float4* s4 = reinterpret_cast<const float4*>(sigma + f * DIM);
        float c = 0.f;
        #pragma unroll 8
        for (int i = 0; i < 32; ++i) {
            float4 m = m4[i], s = s4[i];
            c += m.x * m.x * s.x * s.x + m.y * m.y * s.y * s.y
               + m.z * m.z * s.z * s.z + m.w * m.w * s.w * s.w;
        }
        g_c[f] = c;
    }
}

// ---------------------------------------------------------------------------
// K1: single-pass TF32 literal GEMM (K=128) + fused tanh/segmented reduce
// ---------------------------------------------------------------------------
#define K1_ST(s) (1024 + (s) * 32768)
#define K1_SMEM  (1024 + 3 * 32768)

__device__ __forceinline__ void k1_prefetch(int kc, uint32_t st, int tid, int rb, int yy) {
    const uint4* asrc = g_xa + (size_t)rb * 4096 + kc * 1024;
    const uint4* bsrc = g_wb + (size_t)yy * 4096 + kc * 1024;
    #pragma unroll
    for (int i = 0; i < 4; ++i) {
        int e = tid + i * 256;
        cpa16(st + e * 16,         asrc + e);
        cpa16(st + 16384 + e * 16, bsrc + e);
    }
}

__global__ __launch_bounds__(256, 2) void k1_tensor(const float* __restrict__ bias) {
    extern __shared__ __align__(1024) char smem[];
    const uint32_t sb = smem_u32(smem);
    float* bs = reinterpret_cast<float*>(smem);

    const int tid  = threadIdx.x;
    const int wid  = tid >> 5;
    const int lane = tid & 31;
    const int rb   = blockIdx.x;
    const int yy   = blockIdx.y;
    const int rowBase = rb * 128;

    int LF, nd, nf, f0g, lb0;
    decode_tile(yy, LF, nd, nf, f0g, lb0);
    const int LIVE = nf * LF;

    if (tid < 128) bs[tid] = (tid < LIVE) ? bias[lb0 + tid] : 0.f;

    k1_prefetch(0, sb + K1_ST(0), tid, rb, yy);
    cpa_commit();
    k1_prefetch(1, sb + K1_ST(1), tid, rb, yy);
    cpa_commit();

    const int wm = wid & 3, wn = wid >> 2;
    const int mrow = wm * 32, ncol = wn * 64;
    const uint32_t aoff = (uint32_t)(wm * 4096 + lane * 16);
    const uint32_t boff = (uint32_t)(16384 + wn * 8192 + lane * 16);

    float acc[8][2][4];
    #pragma unroll
    for (int nt = 0; nt < 8; ++nt)
        #pragma unroll
        for (int mt = 0; mt < 2; ++mt)
            #pragma unroll
            for (int j = 0; j < 4; ++j) acc[nt][mt][j] = 0.f;

    #pragma unroll
    for (int kc = 0; kc < 4; ++kc) {
        if (kc < 3) cpa_wait1(); else cpa_wait0();
        __syncthreads();
        if (kc < 2) {
            k1_prefetch(kc + 2, sb + K1_ST((kc + 2) % 3), tid, rb, yy);
            cpa_commit();
        }
        const char* st = smem + K1_ST(kc % 3);
        #pragma unroll
        for (int ks = 0; ks < 4; ++ks) {
            uint4 av[2];
            av[0] = *reinterpret_cast<const uint4*>(st + aoff + ks * 512);
            av[1] = *reinterpret_cast<const uint4*>(st + aoff + 2048 + ks * 512);
            #pragma unroll
            for (int p = 0; p < 4; ++p) {
                uint4 bv = *reinterpret_cast<const uint4*>(st + boff + ks * 2048 + p * 512);
                #pragma unroll
                for (int mt = 0; mt < 2; ++mt) {
                    mma_tf32(acc[2*p    ][mt], av[mt], bv.x, bv.y);
                    mma_tf32(acc[2*p + 1][mt], av[mt], bv.z, bv.w);
                }
            }
        }
    }
    __syncthreads();

    float* ct = reinterpret_cast<float*>(smem + K1_ST(0));
    {
        const int gidr = lane >> 2, tig = lane & 3;
        #pragma unroll
        for (int nt = 0; nt < 8; ++nt) {
            const int c0 = ncol + nt * 8 + 2 * tig;
            #pragma unroll
            for (int mt = 0; mt < 2; ++mt) {
                const int r0 = mrow + mt * 16 + gidr;
                ct[r0 * 130 + c0]           = ftanh(acc[nt][mt][0] + bs[c0]);
                ct[r0 * 130 + c0 + 1]       = ftanh(acc[nt][mt][1] + bs[c0 + 1]);
                ct[(r0 + 8) * 130 + c0]     = ftanh(acc[nt][mt][2] + bs[c0]);
                ct[(r0 + 8) * 130 + c0 + 1] = ftanh(acc[nt][mt][3] + bs[c0 + 1]);
            }
        }
    }
    __syncthreads();

    for (int task = tid; task < 128 * nf; task += 256) {
        const int row = task & 127;
        const int fi  = task >> 7;
        const float* cr = &ct[row * 130 + fi * LF];
        float fs = 0.f;
        int off = 0;
        #pragma unroll
        for (int dd = 0; dd < 3; ++dd) {
            const int d = 2 + 2 * dd;
            for (int c = 0; c < nd; ++c) {
                float sA = 0.f;
                #pragma unroll
                for (int u = 0; u < 6; ++u)
                    if (u < d) sA += cr[off + u];
                fs += ftanh(sA - (float)d + 1.5f);
                off += d;
            }
        }
        g_dnnf[(size_t)(rowBase + row) * NFORM + f0g + fi] =
            ftanh(fs + 3.0f * (float)nd - 1.5f);
    }
}

// ---------------------------------------------------------------------------
// K2 (TF32, K=256): v -> loc -> row softmax -> g_loc
// ---------------------------------------------------------------------------
#define K2_ST(s) (1024 + (s) * 36864)
#define K2_SMEM  (1024 + 3 * 36864)

__device__ __forceinline__ void k2_prefetch(int kc, uint32_t st, int tid, int xb) {
    const uint4* asrc = g_xa2 + (size_t)xb * 2048 + kc * 256;
    const uint4* bsrc = g_b2 + (size_t)kc * 2048;
    cpa16(st + tid * 16, asrc + tid);
    #pragma unroll
    for (int i = 0; i < 8; ++i) {
        int e = tid + i * 256;
        cpa16(st + 4096 + e * 16, bsrc + e);
    }
}

__global__ __launch_bounds__(256) void k2_loc(const float* __restrict__ temp) {
    extern __shared__ __align__(1024) char smem[];
    const uint32_t sb = smem_u32(smem);
    float* scr = reinterpret_cast<float*>(smem);

    const int tid  = threadIdx.x;
    const int wid  = tid >> 5;
    const int lane = tid & 31;
    const int xb   = blockIdx.x;
    const int rowBase = xb * 32;

    k2_prefetch(0, sb + K2_ST(0), tid, xb);
    cpa_commit();
    k2_prefetch(1, sb + K2_ST(1), tid, xb);
    cpa_commit();

    const int wm = wid & 1, wn = wid >> 1;
    const int mrow = wm * 16, ncol = wn * 64;
    const uint32_t aoff = (uint32_t)(wm * 2048 + lane * 16);
    const uint32_t boff = (uint32_t)(4096 + wn * 8192 + lane * 16);

    float acc[8][4];
    #pragma unroll
    for (int nt = 0; nt < 8; ++nt)
        #pragma unroll
        for (int j = 0; j < 4; ++j) acc[nt][j] = 0.f;

    #pragma unroll
    for (int kc = 0; kc < 8; ++kc) {
        if (kc < 7) cpa_wait1(); else cpa_wait0();
        __syncthreads();
        if (kc < 6) {
            k2_prefetch(kc + 2, sb + K2_ST((kc + 2) % 3), tid, xb);
            cpa_commit();
        }
        const char* st = smem + K2_ST(kc % 3);
        #pragma unroll
        for (int ks = 0; ks < 4; ++ks) {
            uint4 av = *reinterpret_cast<const uint4*>(st + aoff + ks * 512);
            #pragma unroll
            for (int p = 0; p < 4; ++p) {
                uint4 bv = *reinterpret_cast<const uint4*>(st + boff + ks * 2048 + p * 512);
                mma_tf32(acc[2*p    ], av, bv.x, bv.y);
                mma_tf32(acc[2*p + 1], av, bv.z, bv.w);
            }
        }
    }

    const float s = 1.f / (1.f + __expf(-temp[0]));
    const int gidr = lane >> 2, tig = lane & 3;

    #pragma unroll
    for (int nt = 0; nt < 8; ++nt)
        #pragma unroll
        for (int j = 0; j < 4; ++j) {
            const int col = ncol + nt * 8 + 2 * tig + (j & 1);
            float v = acc[nt][j] + __ldg(&g_c[col]);
            acc[nt][j] = s * __expf(-__fsqrt_rn(fmaxf(v, 0.f)));
        }

    float rmax[2], rsum[2];
    #pragma unroll
    for (int hf = 0; hf < 2; ++hf) {
        float m = -1e30f;
        #pragma unroll
        for (int nt = 0; nt < 8; ++nt) {
            m = fmaxf(m, acc[nt][2*hf]);
            m = fmaxf(m, acc[nt][2*hf + 1]);
        }
        m = fmaxf(m, __shfl_xor_sync(0xFFFFFFFFu, m, 1));
        m = fmaxf(m, __shfl_xor_sync(0xFFFFFFFFu, m, 2));
        if (tig == 0) scr[(mrow + gidr + hf * 8) * 4 + wn] = m;
    }
    __syncthreads();
    #pragma unroll
    for (int hf = 0; hf < 2; ++hf) {
        const float* p = &scr[(mrow + gidr + hf * 8) * 4];
        rmax[hf] = fmaxf(fmaxf(p[0], p[1]), fmaxf(p[2], p[3]));
    }
    __syncthreads();

    #pragma unroll
    for (int hf = 0; hf < 2; ++hf) {
        float sm = 0.f;
        #pragma unroll
        for (int nt = 0; nt < 8; ++nt) {
            acc[nt][2*hf]     = __expf(acc[nt][2*hf]     - rmax[hf]);
            acc[nt][2*hf + 1] = __expf(acc[nt][2*hf + 1] - rmax[hf]);
            sm += acc[nt][2*hf] + acc[nt][2*hf + 1];
        }
        sm += __shfl_xor_sync(0xFFFFFFFFu, sm, 1);
        sm += __shfl_xor_sync(0xFFFFFFFFu, sm, 2);
        if (tig == 0) scr[(mrow + gidr + hf * 8) * 4 + wn] = sm;
    }
    __syncthreads();
    #pragma unroll
    for (int hf = 0; hf < 2; ++hf) {
        const float* p = &scr[(mrow + gidr + hf * 8) * 4];
        rsum[hf] = 1.f / (p[0] + p[1] + p[2] + p[3]);
    }

    #pragma unroll
    for (int hf = 0; hf < 2; ++hf) {
        const size_t grow = (size_t)(rowBase + mrow + gidr + hf * 8);
        const float inv = rsum[hf];
        #pragma unroll
        for (int nt = 0; nt < 8; ++nt) {
            const int col = ncol + nt * 8 + 2 * tig;
            const size_t idx = grow * NFORM + col;
            g_loc[idx]     = acc[nt][2*hf]     * inv;
            g_loc[idx + 1] = acc[nt][2*hf + 1] * inv;
        }
    }
}

// ---------------------------------------------------------------------------
// K3: out = dnnf * loc
// ---------------------------------------------------------------------------
__global__ __launch_bounds__(256) void k3_mul(float* __restrict__ out) {
    const size_t i = (size_t)blockIdx.x * 256 + threadIdx.x;
    float4 a = reinterpret_cast<const float4*>(g_dnnf)[i];
    float4 b = reinterpret_cast<const float4*>(g_loc)[i];
    reinterpret_cast<float4*>(out)[i] =
        make_float4(a.x * b.x, a.y * b.y, a.z * b.z, a.w * b.w);
}

// ---------------------------------------------------------------------------
extern "C" void kernel_launch(void* const* d_in, const int* in_sizes, int n_in,
                              void* d_out, int out_size) {
    const float* x     = (const float*)d_in[0];
    const float* w     = (const float*)d_in[1];
    const float* bias  = (const float*)d_in[2];
    const float* lm    = (const float*)d_in[3];
    const float* mu    = (const float*)d_in[4];
    const float* sigma = (const float*)d_in[5];
    const float* temp  = (const float*)d_in[6];
    float* out = (float*)d_out;

    cudaFuncSetAttribute(k0_prep_xa, cudaFuncAttributeMaxDynamicSharedMemorySize, PREP2_SMEM);
    cudaFuncSetAttribute(k0_prep_wb, cudaFuncAttributeMaxDynamicSharedMemorySize, PREP_SMEM);
    cudaFuncSetAttribute(k1_tensor,  cudaFuncAttributeMaxDynamicSharedMemorySize, K1_SMEM);
    cudaFuncSetAttribute(k2_loc,     cudaFuncAttributeMaxDynamicSharedMemorySize, K2_SMEM);

    cudaStream_t s2;
    cudaStreamCreateWithFlags(&s2, cudaStreamNonBlocking);
    cudaEvent_t evFork, evXA, evK2;
    cudaEventCreateWithFlags(&evFork, cudaEventDisableTiming);
    cudaEventCreateWithFlags(&evXA,  cudaEventDisableTiming);
    cudaEventCreateWithFlags(&evK2,  cudaEventDisableTiming);

    // fork s2 from main at the very start
    cudaEventRecord(evFork, 0);
    cudaStreamWaitEvent(s2, evFork, 0);

    // s2: prep_xa -> (xa ready) -> b2c -> k2_loc      (concurrent with wb/k1)
    k0_prep_xa<<<128, 256, PREP2_SMEM, s2>>>(x);
    cudaEventRecord(evXA, s2);
    k0_prep_b2c<<<9, 256, 0, s2>>>(mu, sigma);
    k2_loc<<<BATCH / 32, 256, K2_SMEM, s2>>>(temp);
    cudaEventRecord(evK2, s2);

    // main: prep_wb (independent) -> wait xa -> k1 -> wait k2 -> k3
    k0_prep_wb<<<99, 256, PREP_SMEM>>>(w, lm);
    cudaStreamWaitEvent(0, evXA, 0);
    k1_tensor<<<dim3(32, 99), 256, K1_SMEM>>>(bias);
    cudaStreamWaitEvent(0, evK2, 0);
    k3_mul<<<BATCH * NFORM / 1024, 256>>>(out);
}

// round 15
// speedup vs baseline: 1.3735x; 1.0051x over previous
#include <cuda_runtime.h>
#include <cuda_bf16.h>
#include <math.h>
#include <stdint.h>

#define BATCH      4096
#define DIM        128
#define NFORM      256
#define NLIT       10752

// ---------------------------------------------------------------------------
// Helpers (portable PTX only: mma.sync / cp.async / cvt.rna.tf32)
// ---------------------------------------------------------------------------
__device__ __forceinline__ float ftanh(float v) {
    float r; asm("tanh.approx.f32 %0, %1;" : "=f"(r) : "f"(v)); return r;
}
__device__ __forceinline__ uint32_t smem_u32(const void* p) {
    uint32_t a;
    asm("{ .reg .u64 t; cvta.to.shared.u64 t, %1; cvt.u32.u64 %0, t; }" : "=r"(a) : "l"(p));
    return a;
}
__device__ __forceinline__ uint32_t rna_tf32(float v) {
    uint32_t r; asm("cvt.rna.tf32.f32 %0, %1;" : "=r"(r) : "f"(v)); return r;
}
__device__ __forceinline__ void mma_tf32(float* c, uint4 a, uint32_t b0, uint32_t b1) {
    asm volatile("mma.sync.aligned.m16n8k8.row.col.f32.tf32.tf32.f32 "
                 "{%0,%1,%2,%3}, {%4,%5,%6,%7}, {%8,%9}, {%0,%1,%2,%3};"
                 : "+f"(c[0]), "+f"(c[1]), "+f"(c[2]), "+f"(c[3])
                 : "r"(a.x), "r"(a.y), "r"(a.z), "r"(a.w), "r"(b0), "r"(b1));
}
__device__ __forceinline__ void cpa16(uint32_t dst, const void* src) {
    asm volatile("cp.async.ca.shared.global [%0], [%1], 16;" :: "r"(dst), "l"(src));
}
__device__ __forceinline__ void cpa_commit() { asm volatile("cp.async.commit_group;"); }
__device__ __forceinline__ void cpa_wait1()  { asm volatile("cp.async.wait_group 1;"); }
__device__ __forceinline__ void cpa_wait0()  { asm volatile("cp.async.wait_group 0;"); }

// ---------------------------------------------------------------------------
// Scratch (device globals)
// ---------------------------------------------------------------------------
__device__ float g_dnnf[BATCH * NFORM];
__device__ float g_loc [BATCH * NFORM];
__device__ float g_c   [NFORM];
__device__ uint4 g_xa [32 * 4096];      // k1 A: tf32 fragments, per 128-row block
__device__ uint4 g_wb [99 * 4096];      // k1 B: tf32 fragments, per yy-tile
__device__ uint4 g_xa2[128 * 2048];     // k2 A: [x^2 || x], per 32-row block
__device__ uint4 g_b2 [8 * 2048];       // k2 B: [sigma^2 ; -2 mu sigma^2]

// ---------------------------------------------------------------------------
// yy-tile decode (k1) — dense packed, 99 tiles
// ---------------------------------------------------------------------------
__device__ __forceinline__ void decode_tile(int yy, int& LF, int& nd, int& nf,
                                            int& f0g, int& lb0) {
    if (yy < 13)      { LF = 24; nd = 2; nf = (yy == 12) ? 4 : 5; f0g = 5 * yy;          lb0 = 120 * yy; }
    else if (yy < 35) { int t = yy - 13; LF = 36; nd = 3; nf = (t == 21) ? 1 : 3; f0g = 64  + 3 * t; lb0 = 1536 + 108 * t; }
    else if (yy < 67) { int t = yy - 35; LF = 48; nd = 4; nf = 2; f0g = 128 + 2 * t; lb0 = 3840 + 96 * t; }
    else              { int t = yy - 67; LF = 60; nd = 5; nf = 2; f0g = 192 + 2 * t; lb0 = 6912 + 120 * t; }
}

// ---------------------------------------------------------------------------
// K0a: x -> k1 A blob (g_xa) + k2 A blob (g_xa2).  grid=128, 32 rows per CTA.
// ---------------------------------------------------------------------------
#define PREP2_SMEM (32 * 132 * 4)
__global__ __launch_bounds__(256) void k0_prep_xa(const float* __restrict__ x) {
    extern __shared__ __align__(16) float xs[];          // [32][132]
    const int xb = blockIdx.x, tid = threadIdx.x;
    const int rb = xb >> 2, sub = xb & 3;
    for (int e = tid; e < 32 * 32; e += 256) {
        int r = e >> 5, c4 = e & 31;
        float4 v = reinterpret_cast<const float4*>(x + (size_t)(xb * 32 + r) * DIM)[c4];
        xs[r * 132 + c4 * 4 + 0] = v.x;
        xs[r * 132 + c4 * 4 + 1] = v.y;
        xs[r * 132 + c4 * 4 + 2] = v.z;
        xs[r * 132 + c4 * 4 + 3] = v.w;
    }
    __syncthreads();
    // k1 blob: 1024 entries (wm == sub)
    #pragma unroll
    for (int i = 0; i < 4; ++i) {
        int o = i * 256 + tid;
        int lane = o & 31, ks = (o >> 5) & 3, mt = (o >> 7) & 1, kc = (o >> 8) & 3;
        int r = mt * 16 + (lane >> 2);
        int c = kc * 32 + ks * 8 + (lane & 3);
        int go = kc * 1024 + sub * 256 + mt * 128 + ks * 32 + lane;
        g_xa[(size_t)rb * 4096 + go] =
            make_uint4(rna_tf32(xs[r * 132 + c]),     rna_tf32(xs[(r + 8) * 132 + c]),
                       rna_tf32(xs[r * 132 + c + 4]), rna_tf32(xs[(r + 8) * 132 + c + 4]));
    }
    // k2 blob: 2048 entries for this 32-row block
    #pragma unroll
    for (int i = 0; i < 8; ++i) {
        int o = i * 256 + tid;
        int lane = o & 31, ks = (o >> 5) & 3, wm = (o >> 7) & 1, kc = (o >> 8) & 7;
        int r = wm * 16 + (lane >> 2);
        int c = kc * 32 + ks * 8 + (lane & 3);
        float v0, v1, v2, v3;
        if (c < 128) {
            float a = xs[r * 132 + c],      b = xs[(r + 8) * 132 + c];
            float d = xs[r * 132 + c + 4],  e = xs[(r + 8) * 132 + c + 4];
            v0 = a * a; v1 = b * b; v2 = d * d; v3 = e * e;
        } else {
            int cc = c - 128;
            v0 = xs[r * 132 + cc];     v1 = xs[(r + 8) * 132 + cc];
            v2 = xs[r * 132 + cc + 4]; v3 = xs[(r + 8) * 132 + cc + 4];
        }
        g_xa2[(size_t)xb * 2048 + o] =
            make_uint4(rna_tf32(v0), rna_tf32(v1), rna_tf32(v2), rna_tf32(v3));
    }
}

// ---------------------------------------------------------------------------
// K0b: masked W -> k1 B blob.  grid (99, 4): CTA (yy, kc) stages only
//   k-rows [kc*32, kc*32+32) and emits its 1024 blob entries.
// ---------------------------------------------------------------------------
#define PREPW_SMEM (32 * 132 * 4)
__global__ __launch_bounds__(256) void k0_prep_wb(const float* __restrict__ w,
                                                  const float* __restrict__ lm) {
    extern __shared__ __align__(16) float ws[];          // [32 k][132 n]
    const int yy = blockIdx.x, kc = blockIdx.y, tid = threadIdx.x;
    int LF, nd, nf, f0g, lb0;
    decode_tile(yy, LF, nd, nf, f0g, lb0);
    const int LIVE = nf * LF;
    for (int e = tid; e < 32 * 128; e += 256) {
        int kl = e >> 7, j = e & 127;
        int k = kc * 32 + kl;
        float val = 0.f;
        if (j < LIVE) {
            int f = f0g + j / LF;
            float mk = (fabsf(lm[k * NFORM + f]) > 1.0f) ? 1.0f : 0.0f;
            val = w[(size_t)k * NLIT + lb0 + j] * mk;
        }
        ws[kl * 132 + j] = val;
    }
    __syncthreads();
    #pragma unroll
    for (int i = 0; i < 4; ++i) {
        int o2 = i * 256 + tid;                           // 0..1023
        int lane = o2 & 31, p = (o2 >> 5) & 3, ks = (o2 >> 7) & 3, wn = (o2 >> 9) & 1;
        int n  = wn * 64 + p * 16 + (lane >> 2);
        int kl = ks * 8 + (lane & 3);
        g_wb[(size_t)yy * 4096 + kc * 1024 + o2] =
            make_uint4(rna_tf32(ws[kl * 132 + n]),     rna_tf32(ws[(kl + 4) * 132 + n]),
                       rna_tf32(ws[kl * 132 + n + 8]), rna_tf32(ws[(kl + 4) * 132 + n + 8]));
    }
}

// ---------------------------------------------------------------------------
// K0c: k2 B blob (g_b2) + c[f].  grid = 9
// ---------------------------------------------------------------------------
__device__ __forceinline__ float b2val(const float* mu, const float* sg, int k, int n) {
    if (k < 128) { float s = sg[n * DIM + k]; return s * s; }
    int kk = k - 128;
    float s = sg[n * DIM + kk];
    return -2.f * mu[n * DIM + kk] * s * s;
}
__global__ __launch_bounds__(256) void k0_prep_b2c(const float* __restrict__ mu,
                                                   const float* __restrict__ sigma) {
    const int b = blockIdx.x, tid = threadIdx.x;
    if (b < 8) {
        #pragma unroll
        for (int i = 0; i < 8; ++i) {
            int o = i * 256 + tid;
            int lane = o & 31, p = (o >> 5) & 3, ks = (o >> 7) & 3, wn = (o >> 9) & 3;
            int n = wn * 64 + p * 16 + (lane >> 2);
            int k = b * 32 + ks * 8 + (lane & 3);
            g_b2[(size_t)b * 2048 + o] =
                make_uint4(rna_tf32(b2val(mu, sigma, k,     n)),
                           rna_tf32(b2val(mu, sigma, k + 4, n)),
                           rna_tf32(b2val(mu, sigma, k,     n + 8)),
                           rna_tf32(b2val(mu, sigma, k + 4, n + 8)));
        }
    } else {
        int f = tid;
        const float4* m4 = reinterpret_cast<const float4*>(mu + f * DIM);
        const float4* s4 = reinterpret_cast<const float4*>(sigma + f * DIM);
        float c = 0.f;
        #pragma unroll 8
        for (int i = 0; i < 32; ++i) {
            float4 m = m4[i], s = s4[i];
            c += m.x * m.x * s.x * s.x + m.y * m.y * s.y * s.y
               + m.z * m.z * s.z * s.z + m.w * m.w * s.w * s.w;
        }
        g_c[f] = c;
    }
}

// ---------------------------------------------------------------------------
// K1: single-pass TF32 literal GEMM (K=128) + fused tanh/segmented reduce
// ---------------------------------------------------------------------------
#define K1_ST(s) (1024 + (s) * 32768)
#define K1_SMEM  (1024 + 3 * 32768)

__device__ __forceinline__ void k1_prefetch(int kc, uint32_t st, int tid, int rb, int yy) {
    const uint4* asrc = g_xa + (size_t)rb * 4096 + kc * 1024;
    const uint4* bsrc = g_wb + (size_t)yy * 4096 + kc * 1024;
    #pragma unroll
    for (int i = 0; i < 4; ++i) {
        int e = tid + i * 256;
        cpa16(st + e * 16,         asrc + e);
        cpa16(st + 16384 + e * 16, bsrc + e);
    }
}

__global__ __launch_bounds__(256, 2) void k1_tensor(const float* __restrict__ bias) {
    extern __shared__ __align__(1024) char smem[];
    const uint32_t sb = smem_u32(smem);
    float* bs = reinterpret_cast<float*>(smem);

    const int tid  = threadIdx.x;
    const int wid  = tid >> 5;
    const int lane = tid & 31;
    const int rb   = blockIdx.x;
    const int yy   = blockIdx.y;
    const int rowBase = rb * 128;

    int LF, nd, nf, f0g, lb0;
    decode_tile(yy, LF, nd, nf, f0g, lb0);
    const int LIVE = nf * LF;

    if (tid < 128) bs[tid] = (tid < LIVE) ? bias[lb0 + tid] : 0.f;

    k1_prefetch(0, sb + K1_ST(0), tid, rb, yy);
    cpa_commit();
    k1_prefetch(1, sb + K1_ST(1), tid, rb, yy);
    cpa_commit();

    const int wm = wid & 3, wn = wid >> 2;
    const int mrow = wm * 32, ncol = wn * 64;
    const uint32_t aoff = (uint32_t)(wm * 4096 + lane * 16);
    const uint32_t boff = (uint32_t)(16384 + wn * 8192 + lane * 16);

    float acc[8][2][4];
    #pragma unroll
    for (int nt = 0; nt < 8; ++nt)
        #pragma unroll
        for (int mt = 0; mt < 2; ++mt)
            #pragma unroll
            for (int j = 0; j < 4; ++j) acc[nt][mt][j] = 0.f;

    #pragma unroll
    for (int kc = 0; kc < 4; ++kc) {
        if (kc < 3) cpa_wait1(); else cpa_wait0();
        __syncthreads();
        if (kc < 2) {
            k1_prefetch(kc + 2, sb + K1_ST((kc + 2) % 3), tid, rb, yy);
            cpa_commit();
        }
        const char* st = smem + K1_ST(kc % 3);
        #pragma unroll
        for (int ks = 0; ks < 4; ++ks) {
            uint4 av[2];
            av[0] = *reinterpret_cast<const uint4*>(st + aoff + ks * 512);
            av[1] = *reinterpret_cast<const uint4*>(st + aoff + 2048 + ks * 512);
            #pragma unroll
            for (int p = 0; p < 4; ++p) {
                uint4 bv = *reinterpret_cast<const uint4*>(st + boff + ks * 2048 + p * 512);
                #pragma unroll
                for (int mt = 0; mt < 2; ++mt) {
                    mma_tf32(acc[2*p    ][mt], av[mt], bv.x, bv.y);
                    mma_tf32(acc[2*p + 1][mt], av[mt], bv.z, bv.w);
                }
            }
        }
    }
    __syncthreads();

    float* ct = reinterpret_cast<float*>(smem + K1_ST(0));
    {
        const int gidr = lane >> 2, tig = lane & 3;
        #pragma unroll
        for (int nt = 0; nt < 8; ++nt) {
            const int c0 = ncol + nt * 8 + 2 * tig;
            #pragma unroll
            for (int mt = 0; mt < 2; ++mt) {
                const int r0 = mrow + mt * 16 + gidr;
                ct[r0 * 130 + c0]           = ftanh(acc[nt][mt][0] + bs[c0]);
                ct[r0 * 130 + c0 + 1]       = ftanh(acc[nt][mt][1] + bs[c0 + 1]);
                ct[(r0 + 8) * 130 + c0]     = ftanh(acc[nt][mt][2] + bs[c0]);
                ct[(r0 + 8) * 130 + c0 + 1] = ftanh(acc[nt][mt][3] + bs[c0 + 1]);
            }
        }
    }
    __syncthreads();

    for (int task = tid; task < 128 * nf; task += 256) {
        const int row = task & 127;
        const int fi  = task >> 7;
        const float* cr = &ct[row * 130 + fi * LF];
        float fs = 0.f;
        int off = 0;
        #pragma unroll
        for (int dd = 0; dd < 3; ++dd) {
            const int d = 2 + 2 * dd;
            for (int c = 0; c < nd; ++c) {
                float sA = 0.f;
                #pragma unroll
                for (int u = 0; u < 6; ++u)
                    if (u < d) sA += cr[off + u];
                fs += ftanh(sA - (float)d + 1.5f);
                off += d;
            }
        }
        g_dnnf[(size_t)(rowBase + row) * NFORM + f0g + fi] =
            ftanh(fs + 3.0f * (float)nd - 1.5f);
    }
}

// ---------------------------------------------------------------------------
// K2 (TF32, K=256): v -> loc -> row softmax -> g_loc
// ---------------------------------------------------------------------------
#define K2_ST(s) (1024 + (s) * 36864)
#define K2_SMEM  (1024 + 3 * 36864)

__device__ __forceinline__ void k2_prefetch(int kc, uint32_t st, int tid, int xb) {
    const uint4* asrc = g_xa2 + (size_t)xb * 2048 + kc * 256;
    const uint4* bsrc = g_b2 + (size_t)kc * 2048;
    cpa16(st + tid * 16, asrc + tid);
    #pragma unroll
    for (int i = 0; i < 8; ++i) {
        int e = tid + i * 256;
        cpa16(st + 4096 + e * 16, bsrc + e);
    }
}

__global__ __launch_bounds__(256) void k2_loc(const float* __restrict__ temp) {
    extern __shared__ __align__(1024) char smem[];
    const uint32_t sb = smem_u32(smem);
    float* scr = reinterpret_cast<float*>(smem);

    const int tid  = threadIdx.x;
    const int wid  = tid >> 5;
    const int lane = tid & 31;
    const int xb   = blockIdx.x;
    const int rowBase = xb * 32;

    k2_prefetch(0, sb + K2_ST(0), tid, xb);
    cpa_commit();
    k2_prefetch(1, sb + K2_ST(1), tid, xb);
    cpa_commit();

    const int wm = wid & 1, wn = wid >> 1;
    const int mrow = wm * 16, ncol = wn * 64;
    const uint32_t aoff = (uint32_t)(wm * 2048 + lane * 16);
    const uint32_t boff = (uint32_t)(4096 + wn * 8192 + lane * 16);

    float acc[8][4];
    #pragma unroll
    for (int nt = 0; nt < 8; ++nt)
        #pragma unroll
        for (int j = 0; j < 4; ++j) acc[nt][j] = 0.f;

    #pragma unroll
    for (int kc = 0; kc < 8; ++kc) {
        if (kc < 7) cpa_wait1(); else cpa_wait0();
        __syncthreads();
        if (kc < 6) {
            k2_prefetch(kc + 2, sb + K2_ST((kc + 2) % 3), tid, xb);
            cpa_commit();
        }
        const char* st = smem + K2_ST(kc % 3);
        #pragma unroll
        for (int ks = 0; ks < 4; ++ks) {
            uint4 av = *reinterpret_cast<const uint4*>(st + aoff + ks * 512);
            #pragma unroll
            for (int p = 0; p < 4; ++p) {
                uint4 bv = *reinterpret_cast<const uint4*>(st + boff + ks * 2048 + p * 512);
                mma_tf32(acc[2*p    ], av, bv.x, bv.y);
                mma_tf32(acc[2*p + 1], av, bv.z, bv.w);
            }
        }
    }

    const float s = 1.f / (1.f + __expf(-temp[0]));
    const int gidr = lane >> 2, tig = lane & 3;

    #pragma unroll
    for (int nt = 0; nt < 8; ++nt)
        #pragma unroll
        for (int j = 0; j < 4; ++j) {
            const int col = ncol + nt * 8 + 2 * tig + (j & 1);
            float v = acc[nt][j] + __ldg(&g_c[col]);
            acc[nt][j] = s * __expf(-__fsqrt_rn(fmaxf(v, 0.f)));
        }

    float rmax[2], rsum[2];
    #pragma unroll
    for (int hf = 0; hf < 2; ++hf) {
        float m = -1e30f;
        #pragma unroll
        for (int nt = 0; nt < 8; ++nt) {
            m = fmaxf(m, acc[nt][2*hf]);
            m = fmaxf(m, acc[nt][2*hf + 1]);
        }
        m = fmaxf(m, __shfl_xor_sync(0xFFFFFFFFu, m, 1));
        m = fmaxf(m, __shfl_xor_sync(0xFFFFFFFFu, m, 2));
        if (tig == 0) scr[(mrow + gidr + hf * 8) * 4 + wn] = m;
    }
    __syncthreads();
    #pragma unroll
    for (int hf = 0; hf < 2; ++hf) {
        const float* p = &scr[(mrow + gidr + hf * 8) * 4];
        rmax[hf] = fmaxf(fmaxf(p[0], p[1]), fmaxf(p[2], p[3]));
    }
    __syncthreads();

    #pragma unroll
    for (int hf = 0; hf < 2; ++hf) {
        float sm = 0.f;
        #pragma unroll
        for (int nt = 0; nt < 8; ++nt) {
            acc[nt][2*hf]     = __expf(acc[nt][2*hf]     - rmax[hf]);
            acc[nt][2*hf + 1] = __expf(acc[nt][2*hf + 1] - rmax[hf]);
            sm += acc[nt][2*hf] + acc[nt][2*hf + 1];
        }
        sm += __shfl_xor_sync(0xFFFFFFFFu, sm, 1);
        sm += __shfl_xor_sync(0xFFFFFFFFu, sm, 2);
        if (tig == 0) scr[(mrow + gidr + hf * 8) * 4 + wn] = sm;
    }
    __syncthreads();
    #pragma unroll
    for (int hf = 0; hf < 2; ++hf) {
        const float* p = &scr[(mrow + gidr + hf * 8) * 4];
        rsum[hf] = 1.f / (p[0] + p[1] + p[2] + p[3]);
    }

    #pragma unroll
    for (int hf = 0; hf < 2; ++hf) {
        const size_t grow = (size_t)(rowBase + mrow + gidr + hf * 8);
        const float inv = rsum[hf];
        #pragma unroll
        for (int nt = 0; nt < 8; ++nt) {
            const int col = ncol + nt * 8 + 2 * tig;
            const size_t idx = grow * NFORM + col;
            g_loc[idx]     = acc[nt][2*hf]     * inv;
            g_loc[idx + 1] = acc[nt][2*hf + 1] * inv;
        }
    }
}

// ---------------------------------------------------------------------------
// K3: out = dnnf * loc
// ---------------------------------------------------------------------------
__global__ __launch_bounds__(256) void k3_mul(float* __restrict__ out) {
    const size_t i = (size_t)blockIdx.x * 256 + threadIdx.x;
    float4 a = reinterpret_cast<const float4*>(g_dnnf)[i];
    float4 b = reinterpret_cast<const float4*>(g_loc)[i];
    reinterpret_cast<float4*>(out)[i] =
        make_float4(a.x * b.x, a.y * b.y, a.z * b.z, a.w * b.w);
}

// ---------------------------------------------------------------------------
extern "C" void kernel_launch(void* const* d_in, const int* in_sizes, int n_in,
                              void* d_out, int out_size) {
    const float* x     = (const float*)d_in[0];
    const float* w     = (const float*)d_in[1];
    const float* bias  = (const float*)d_in[2];
    const float* lm    = (const float*)d_in[3];
    const float* mu    = (const float*)d_in[4];
    const float* sigma = (const float*)d_in[5];
    const float* temp  = (const float*)d_in[6];
    float* out = (float*)d_out;

    cudaFuncSetAttribute(k0_prep_xa, cudaFuncAttributeMaxDynamicSharedMemorySize, PREP2_SMEM);
    cudaFuncSetAttribute(k0_prep_wb, cudaFuncAttributeMaxDynamicSharedMemorySize, PREPW_SMEM);
    cudaFuncSetAttribute(k1_tensor,  cudaFuncAttributeMaxDynamicSharedMemorySize, K1_SMEM);
    cudaFuncSetAttribute(k2_loc,     cudaFuncAttributeMaxDynamicSharedMemorySize, K2_SMEM);

    cudaStream_t s2;
    cudaStreamCreateWithFlags(&s2, cudaStreamNonBlocking);
    cudaEvent_t evFork, evXA, evK2;
    cudaEventCreateWithFlags(&evFork, cudaEventDisableTiming);
    cudaEventCreateWithFlags(&evXA,  cudaEventDisableTiming);
    cudaEventCreateWithFlags(&evK2,  cudaEventDisableTiming);

    // fork s2 from main at the very start
    cudaEventRecord(evFork, 0);
    cudaStreamWaitEvent(s2, evFork, 0);

    // s2: prep_xa -> (xa ready) -> b2c -> k2_loc      (concurrent with wb/k1)
    k0_prep_xa<<<128, 256, PREP2_SMEM, s2>>>(x);
    cudaEventRecord(evXA, s2);
    k0_prep_b2c<<<9, 256, 0, s2>>>(mu, sigma);
    k2_loc<<<BATCH / 32, 256, K2_SMEM, s2>>>(temp);
    cudaEventRecord(evK2, s2);

    // main: prep_wb (4x parallel) -> wait xa -> k1 -> wait k2 -> k3
    k0_prep_wb<<<dim3(99, 4), 256, PREPW_SMEM>>>(w, lm);
    cudaStreamWaitEvent(0, evXA, 0);
    k1_tensor<<<dim3(32, 99), 256, K1_SMEM>>>(bias);
    cudaStreamWaitEvent(0, evK2, 0);
    k3_mul<<<BATCH * NFORM / 1024, 256>>>(out);
}